// round 4
// baseline (speedup 1.0000x reference)
#include <cuda_runtime.h>
#include <cuda_bf16.h>
#include <cstdint>

// ---------------------------------------------------------------------------
// Problem dims
// ---------------------------------------------------------------------------
#define BATCH   16
#define SEQ     256
#define EMBED   512
#define HIDDEN  1024
#define GATES   (4 * HIDDEN)        // 4096
#define VOCAB   32000
#define MROWS   (BATCH * SEQ)       // 4096
#define NBLK    128                 // persistent LSTM grid size

// ---------------------------------------------------------------------------
// Scratch (device globals; no runtime allocation allowed)
// ---------------------------------------------------------------------------
__device__ float g_xemb  [MROWS * EMBED];     //  8 MB
__device__ float g_gatesx[MROWS * GATES];     // 64 MB: input-projection preacts (+biases)
__device__ float g_hs0   [MROWS * HIDDEN];    // 16 MB
__device__ float g_hs1   [MROWS * HIDDEN];    // 16 MB
__device__ float g_hbuf  [2][BATCH * HIDDEN]; // ping-pong h state
__device__ unsigned g_cnt;                    // grid barrier counter
__device__ volatile unsigned g_gen;           // grid barrier generation (monotonic)

// ---------------------------------------------------------------------------
// Packed f32x2 helpers (FFMA2 — 2x fp32 FMA throughput; PTX-only)
// ---------------------------------------------------------------------------
__device__ __forceinline__ void ffma2(unsigned long long& d,
                                      unsigned long long a,
                                      unsigned long long b) {
    asm("fma.rn.f32x2 %0, %1, %2, %0;" : "+l"(d) : "l"(a), "l"(b));
}
__device__ __forceinline__ unsigned long long pack2(float v) {
    unsigned long long r;
    unsigned int u = __float_as_uint(v);
    asm("mov.b64 %0, {%1, %1};" : "=l"(r) : "r"(u));
    return r;
}
__device__ __forceinline__ float2 unpack2(unsigned long long v) {
    unsigned int lo, hi;
    asm("mov.b64 {%0, %1}, %2;" : "=r"(lo), "=r"(hi) : "l"(v));
    return make_float2(__uint_as_float(lo), __uint_as_float(hi));
}

// ---------------------------------------------------------------------------
// Grid-wide barrier (sense via monotonically increasing generation).
// All NBLK blocks are guaranteed co-resident (NBLK <= SM count, tiny regs).
// ---------------------------------------------------------------------------
__device__ __forceinline__ void grid_bar(unsigned target) {
    __threadfence();
    __syncthreads();
    if (threadIdx.x == 0) {
        unsigned arr = atomicAdd(&g_cnt, 1u);
        if (arr == NBLK - 1) {
            g_cnt = 0;
            __threadfence();
            g_gen = target;            // release
        } else {
            while ((int)(g_gen - target) < 0) {}
            __threadfence();
        }
    }
    __syncthreads();
}

// ---------------------------------------------------------------------------
// Embedding gather (float4 rows)
// ---------------------------------------------------------------------------
__global__ void embed_kernel(const int* __restrict__ x,
                             const float* __restrict__ emb,
                             float* __restrict__ out) {
    int idx = blockIdx.x * 256 + threadIdx.x;   // over float4 units
    int row = idx >> 7;                         // EMBED/4 = 128 per row
    int e4  = idx & 127;
    const float4* src = (const float4*)(emb + ((size_t)x[row] << 9));
    ((float4*)out)[idx] = src[e4];
}

// ---------------------------------------------------------------------------
// fp32 GEMM:  C[M,N] = A[M,K] @ W[N,K]^T + b1 (+ b2)
// 128x128x16 tile, 256 threads, 16(m as 8 f32x2-pairs) x 4(n) micro-tile.
// Requires M%128==0, N%128==0, K%16==0.
// ---------------------------------------------------------------------------
__global__ __launch_bounds__(256, 2)
void gemm_abT(const float* __restrict__ A, const float* __restrict__ W,
              const float* __restrict__ b1, const float* __restrict__ b2,
              float* __restrict__ C, int M, int N, int K) {
    __shared__ float As[16][132];
    __shared__ float Ws[16][132];

    int tid = threadIdx.x;
    int m0 = blockIdx.y << 7;
    int n0 = blockIdx.x << 7;
    int lr = tid >> 2;              // 0..63
    int lc = (tid & 3) << 2;        // 0,4,8,12
    int ty = tid >> 5;              // 0..7  -> 16 rows
    int tx = tid & 31;              // 0..31 -> 4 cols

    unsigned long long acc[4][8];
#pragma unroll
    for (int j = 0; j < 4; j++)
#pragma unroll
        for (int i = 0; i < 8; i++) acc[j][i] = 0ull;

    const float* Ar0 = A + (size_t)(m0 + lr) * K;
    const float* Ar1 = A + (size_t)(m0 + lr + 64) * K;
    const float* Wr0 = W + (size_t)(n0 + lr) * K;
    const float* Wr1 = W + (size_t)(n0 + lr + 64) * K;

    for (int k0 = 0; k0 < K; k0 += 16) {
        float4 a0 = *(const float4*)(Ar0 + k0 + lc);
        float4 a1 = *(const float4*)(Ar1 + k0 + lc);
        float4 w0 = *(const float4*)(Wr0 + k0 + lc);
        float4 w1 = *(const float4*)(Wr1 + k0 + lc);
        __syncthreads();
        As[lc+0][lr] = a0.x; As[lc+1][lr] = a0.y; As[lc+2][lr] = a0.z; As[lc+3][lr] = a0.w;
        As[lc+0][lr+64] = a1.x; As[lc+1][lr+64] = a1.y; As[lc+2][lr+64] = a1.z; As[lc+3][lr+64] = a1.w;
        Ws[lc+0][lr] = w0.x; Ws[lc+1][lr] = w0.y; Ws[lc+2][lr] = w0.z; Ws[lc+3][lr] = w0.w;
        Ws[lc+0][lr+64] = w1.x; Ws[lc+1][lr+64] = w1.y; Ws[lc+2][lr+64] = w1.z; Ws[lc+3][lr+64] = w1.w;
        __syncthreads();

#pragma unroll
        for (int kk = 0; kk < 16; kk++) {
            ulonglong2 ap01 = *(const ulonglong2*)&As[kk][ty*16 + 0];
            ulonglong2 ap23 = *(const ulonglong2*)&As[kk][ty*16 + 4];
            ulonglong2 ap45 = *(const ulonglong2*)&As[kk][ty*16 + 8];
            ulonglong2 ap67 = *(const ulonglong2*)&As[kk][ty*16 + 12];
            float4 wv = *(const float4*)&Ws[kk][tx*4];
            unsigned long long wp0 = pack2(wv.x), wp1 = pack2(wv.y);
            unsigned long long wp2 = pack2(wv.z), wp3 = pack2(wv.w);
            unsigned long long ap[8] = {ap01.x, ap01.y, ap23.x, ap23.y,
                                        ap45.x, ap45.y, ap67.x, ap67.y};
#pragma unroll
            for (int i = 0; i < 8; i++) {
                ffma2(acc[0][i], wp0, ap[i]);
                ffma2(acc[1][i], wp1, ap[i]);
                ffma2(acc[2][i], wp2, ap[i]);
                ffma2(acc[3][i], wp3, ap[i]);
            }
        }
    }

    int n = n0 + (tx << 2);
    float4 bv = *(const float4*)(b1 + n);
    if (b2) {
        float4 t2 = *(const float4*)(b2 + n);
        bv.x += t2.x; bv.y += t2.y; bv.z += t2.z; bv.w += t2.w;
    }
#pragma unroll
    for (int i = 0; i < 8; i++) {
        float2 c0f = unpack2(acc[0][i]);
        float2 c1f = unpack2(acc[1][i]);
        float2 c2f = unpack2(acc[2][i]);
        float2 c3f = unpack2(acc[3][i]);
        int r0 = m0 + ty*16 + 2*i;
        float4 o0 = make_float4(c0f.x + bv.x, c1f.x + bv.y, c2f.x + bv.z, c3f.x + bv.w);
        float4 o1 = make_float4(c0f.y + bv.x, c1f.y + bv.y, c2f.y + bv.z, c3f.y + bv.w);
        *(float4*)(C + (size_t)r0 * N + n) = o0;
        *(float4*)(C + (size_t)(r0 + 1) * N + n) = o1;
    }
}

// ---------------------------------------------------------------------------
// Persistent LSTM layer: 128 blocks x 256 threads, whole sequence in one
// launch. Each block owns 8 hidden columns (x4 gates = 32 W_hh rows); each
// thread = 1 row x 1 batch-pair. h ping-pongs in global (read via __ldcg:
// L1 is not coherent across SMs); c lives in SMEM for the whole layer.
// One grid barrier per timestep.
// ---------------------------------------------------------------------------
__global__ __launch_bounds__(256)
void lstm_layer(const float* __restrict__ Whh,
                const float* __restrict__ gatesx,
                const float* __restrict__ h0l, const float* __restrict__ c0l,
                float* __restrict__ hs,
                float* __restrict__ hT, float* __restrict__ cT) {
    __shared__ float h_sm[512][18];
    __shared__ float gate_sm[32][17];
    __shared__ float c_sm[128];
    __shared__ unsigned base_sh;

    int tid = threadIdx.x;
    int bid = blockIdx.x;

    if (tid == 0) base_sh = g_gen;   // stable: only changes after all blocks arrive
    __syncthreads();
    unsigned tgt = base_sh;

    // init state
    if (tid < 128) {
        g_hbuf[0][bid * 128 + tid] = h0l[bid * 128 + tid];
        int b = tid >> 3, cc = tid & 7;
        c_sm[tid] = c0l[b * HIDDEN + bid * 8 + cc];
    }
    grid_bar(++tgt);

    int lrow = tid >> 3;             // 0..31
    int pr2  = (tid & 7) << 1;       // batch-pair offset
    int q    = lrow >> 3;            // gate index 0..3
    int col  = bid * 8 + (lrow & 7); // hidden column
    const float* wr_base = Whh + (size_t)(q * HIDDEN + col) * HIDDEN;

    for (int t = 0; t < SEQ; t++) {
        const float* hin  = g_hbuf[t & 1];
        float*       hout = g_hbuf[(t + 1) & 1];
        unsigned long long acc = 0ull;

#pragma unroll
        for (int kc = 0; kc < 2; kc++) {
            __syncthreads();
            // load h chunk [512 k x 16 b] transposed into SMEM (L2-fresh)
            for (int i = tid; i < 2048; i += 256) {
                int b  = i >> 7;
                int k4 = (i & 127) << 2;
                float4 v = __ldcg((const float4*)(hin + b * HIDDEN + kc * 512 + k4));
                h_sm[k4 + 0][b] = v.x; h_sm[k4 + 1][b] = v.y;
                h_sm[k4 + 2][b] = v.z; h_sm[k4 + 3][b] = v.w;
            }
            __syncthreads();
            const float* wr = wr_base + kc * 512;
#pragma unroll 4
            for (int k = 0; k < 512; k += 4) {
                float4 w = *(const float4*)(wr + k);
                ffma2(acc, pack2(w.x), *(const unsigned long long*)&h_sm[k + 0][pr2]);
                ffma2(acc, pack2(w.y), *(const unsigned long long*)&h_sm[k + 1][pr2]);
                ffma2(acc, pack2(w.z), *(const unsigned long long*)&h_sm[k + 2][pr2]);
                ffma2(acc, pack2(w.w), *(const unsigned long long*)&h_sm[k + 3][pr2]);
            }
        }

        float2 u = unpack2(acc);
        gate_sm[lrow][pr2]     = u.x;
        gate_sm[lrow][pr2 + 1] = u.y;
        __syncthreads();

        if (tid < 128) {
            int b = tid >> 3, cc = tid & 7;
            int colp = bid * 8 + cc;
            size_t gb = (size_t)(b * SEQ + t) * GATES;
            float gi = gate_sm[cc][b]      + gatesx[gb + colp];
            float gf = gate_sm[8 + cc][b]  + gatesx[gb + 1024 + colp];
            float gg = gate_sm[16 + cc][b] + gatesx[gb + 2048 + colp];
            float go = gate_sm[24 + cc][b] + gatesx[gb + 3072 + colp];
            float si = 1.f / (1.f + expf(-gi));
            float sf = 1.f / (1.f + expf(-gf));
            float tg = tanhf(gg);
            float so = 1.f / (1.f + expf(-go));
            float cn = sf * c_sm[tid] + si * tg;
            c_sm[tid] = cn;
            float hn = so * tanhf(cn);
            hout[b * HIDDEN + colp] = hn;
            hs[(size_t)(b * SEQ + t) * HIDDEN + colp] = hn;
        }
        grid_bar(++tgt);
    }

    // final state writeout (SEQ even -> final h in buffer 0)
    if (tid < 128) {
        hT[bid * 128 + tid] = __ldcg(&g_hbuf[0][bid * 128 + tid]);
        int b = tid >> 3;
        cT[b * HIDDEN + bid * 8 + (tid & 7)] = c_sm[tid];
    }
}

// ---------------------------------------------------------------------------
// Launch: 6 graph nodes total (keeps graph upload device-alloc at zero)
// ---------------------------------------------------------------------------
extern "C" void kernel_launch(void* const* d_in, const int* in_sizes, int n_in,
                              void* d_out, int out_size) {
    const int*   x     = (const int*)  d_in[0];
    const float* h0    = (const float*)d_in[1];
    const float* c0    = (const float*)d_in[2];
    const float* emb   = (const float*)d_in[3];
    const float* W_ih0 = (const float*)d_in[4];
    const float* W_hh0 = (const float*)d_in[5];
    const float* b_ih0 = (const float*)d_in[6];
    const float* b_hh0 = (const float*)d_in[7];
    const float* W_ih1 = (const float*)d_in[8];
    const float* W_hh1 = (const float*)d_in[9];
    const float* b_ih1 = (const float*)d_in[10];
    const float* b_hh1 = (const float*)d_in[11];
    const float* fc_W  = (const float*)d_in[12];
    const float* fc_b  = (const float*)d_in[13];

    float* out    = (float*)d_out;
    float* logits = out;
    float* hT     = out + (size_t)MROWS * VOCAB;
    float* cT     = hT + 2 * BATCH * HIDDEN;

    float *p_xemb, *p_gatesx, *p_hs0, *p_hs1;
    cudaGetSymbolAddress((void**)&p_xemb,   g_xemb);
    cudaGetSymbolAddress((void**)&p_gatesx, g_gatesx);
    cudaGetSymbolAddress((void**)&p_hs0,    g_hs0);
    cudaGetSymbolAddress((void**)&p_hs1,    g_hs1);

    const int SH = BATCH * HIDDEN;

    // 1) embedding
    embed_kernel<<<(MROWS * (EMBED / 4)) / 256, 256>>>(x, emb, p_xemb);

    // 2) layer-0 input projection (both biases folded in)
    gemm_abT<<<dim3(GATES / 128, MROWS / 128), 256>>>(
        p_xemb, W_ih0, b_ih0, b_hh0, p_gatesx, MROWS, GATES, EMBED);

    // 3) layer-0 recurrence (persistent)
    lstm_layer<<<NBLK, 256>>>(W_hh0, p_gatesx, h0, c0, p_hs0, hT, cT);

    // 4) layer-1 input projection
    gemm_abT<<<dim3(GATES / 128, MROWS / 128), 256>>>(
        p_hs0, W_ih1, b_ih1, b_hh1, p_gatesx, MROWS, GATES, HIDDEN);

    // 5) layer-1 recurrence
    lstm_layer<<<NBLK, 256>>>(W_hh1, p_gatesx, h0 + SH, c0 + SH,
                              p_hs1, hT + SH, cT + SH);

    // 6) FC head
    gemm_abT<<<dim3(VOCAB / 128, MROWS / 128), 256>>>(
        p_hs1, fc_W, fc_b, nullptr, logits, MROWS, VOCAB, HIDDEN);
}

// round 6
// speedup vs baseline: 3.2104x; 3.2104x over previous
#include <cuda_runtime.h>
#include <cuda_bf16.h>
#include <cstdint>

#define BATCH   16
#define SEQ     256
#define EMBED   512
#define HIDDEN  1024
#define GATES   (4 * HIDDEN)
#define VOCAB   32000
#define MROWS   (BATCH * SEQ)
#define NBLK    128
#define LROW    1152   // padded/permuted h_dup row length (u64 units)
typedef unsigned long long ull;

// ------------------------- scratch (device globals) -------------------------
__device__ float g_gatesx[MROWS * GATES];
__device__ float g_hs0[MROWS * HIDDEN];
__device__ float g_hs1[MROWS * HIDDEN];
__device__ __nv_bfloat16 g_ah[MROWS * HIDDEN];
__device__ __nv_bfloat16 g_al[MROWS * HIDDEN];
__device__ __nv_bfloat16 g_wh[(size_t)VOCAB * HIDDEN];
__device__ __nv_bfloat16 g_wl[(size_t)VOCAB * HIDDEN];
__device__ float g_hbuf[2][BATCH * HIDDEN];
__device__ unsigned g_cnt;
__device__ volatile unsigned g_gen;

// ------------------------- f32x2 helpers -------------------------
__device__ __forceinline__ void ffma2(ull& d, ull a, ull b) {
    asm("fma.rn.f32x2 %0, %1, %2, %0;" : "+l"(d) : "l"(a), "l"(b));
}
__device__ __forceinline__ ull pack_dup(float v) {
    ull r; unsigned u = __float_as_uint(v);
    asm("mov.b64 %0, {%1, %1};" : "=l"(r) : "r"(u)); return r;
}
__device__ __forceinline__ ull pack_pair(float a, float b) {
    ull r;
    asm("mov.b64 %0, {%1, %2};" : "=l"(r) : "r"(__float_as_uint(a)), "r"(__float_as_uint(b)));
    return r;
}
__device__ __forceinline__ float2 unpack2(ull v) {
    unsigned lo, hi;
    asm("mov.b64 {%0, %1}, %2;" : "=r"(lo), "=r"(hi) : "l"(v));
    return make_float2(__uint_as_float(lo), __uint_as_float(hi));
}

// ------------------------- HMMA / smem helpers (plain sm_103-safe) ----------
__device__ __forceinline__ uint32_t smem_u32(const void* p) {
    uint32_t a;
    asm("{ .reg .u64 t; cvta.to.shared.u64 t, %1; cvt.u32.u64 %0, t; }" : "=r"(a) : "l"(p));
    return a;
}
__device__ __forceinline__ void mma_bf16(float* d, const unsigned* a, const unsigned* b) {
    asm volatile("mma.sync.aligned.m16n8k16.row.col.f32.bf16.bf16.f32 "
        "{%0,%1,%2,%3}, {%4,%5,%6,%7}, {%8,%9}, {%0,%1,%2,%3};"
        : "+f"(d[0]), "+f"(d[1]), "+f"(d[2]), "+f"(d[3])
        : "r"(a[0]), "r"(a[1]), "r"(a[2]), "r"(a[3]), "r"(b[0]), "r"(b[1]));
}
__device__ __forceinline__ void ldsm_x4(unsigned* r, uint32_t addr) {
    asm volatile("ldmatrix.sync.aligned.m8n8.x4.shared.b16 {%0,%1,%2,%3}, [%4];"
        : "=r"(r[0]), "=r"(r[1]), "=r"(r[2]), "=r"(r[3]) : "r"(addr));
}
__device__ __forceinline__ void cp16(uint32_t dst, const void* src) {
    asm volatile("cp.async.cg.shared.global [%0], [%1], 16;" :: "r"(dst), "l"(src));
}
#define CP_COMMIT()  asm volatile("cp.async.commit_group;" ::: "memory")
#define CP_WAIT(n)   asm volatile("cp.async.wait_group %0;" :: "n"(n) : "memory")
#define SW128(o) ((o) ^ (((o) >> 3) & 0x70))

// ------------------------- grid barrier -------------------------
__device__ __forceinline__ void grid_bar(unsigned target) {
    __threadfence();
    __syncthreads();
    if (threadIdx.x == 0) {
        unsigned arr = atomicAdd(&g_cnt, 1u);
        if (arr == NBLK - 1) { g_cnt = 0; __threadfence(); g_gen = target; }
        else { while ((int)(g_gen - target) < 0) {} __threadfence(); }
    }
    __syncthreads();
}

// ------------------------- fp32 -> bf16 hi/lo split -------------------------
__device__ __forceinline__ void split8(float4 v0, float4 v1, uint4& hi, uint4& lo) {
    float f[8] = {v0.x, v0.y, v0.z, v0.w, v1.x, v1.y, v1.z, v1.w};
    unsigned short h[8], l[8];
#pragma unroll
    for (int i = 0; i < 8; i++) {
        __nv_bfloat16 bh = __float2bfloat16_rn(f[i]);
        __nv_bfloat16 bl = __float2bfloat16_rn(f[i] - __bfloat162float(bh));
        h[i] = __bfloat16_as_ushort(bh); l[i] = __bfloat16_as_ushort(bl);
    }
    hi = make_uint4(h[0]|((uint32_t)h[1]<<16), h[2]|((uint32_t)h[3]<<16),
                    h[4]|((uint32_t)h[5]<<16), h[6]|((uint32_t)h[7]<<16));
    lo = make_uint4(l[0]|((uint32_t)l[1]<<16), l[2]|((uint32_t)l[3]<<16),
                    l[4]|((uint32_t)l[5]<<16), l[6]|((uint32_t)l[7]<<16));
}

__global__ void cvt_hilo(const float* __restrict__ src,
                         __nv_bfloat16* __restrict__ hi,
                         __nv_bfloat16* __restrict__ lo, int n8) {
    int i = blockIdx.x * 256 + threadIdx.x;
    if (i >= n8) return;
    const float4* s = (const float4*)src + 2 * (size_t)i;
    uint4 h, l; split8(s[0], s[1], h, l);
    ((uint4*)hi)[i] = h; ((uint4*)lo)[i] = l;
}

__global__ void embed_cvt(const int* __restrict__ x, const float* __restrict__ emb,
                          __nv_bfloat16* __restrict__ hi, __nv_bfloat16* __restrict__ lo) {
    int idx = blockIdx.x * 256 + threadIdx.x;   // 8-elem units
    int row = idx >> 6;                          // EMBED/8 = 64 per row
    int e8  = idx & 63;
    const float4* s = (const float4*)(emb + ((size_t)x[row] << 9)) + 2 * e8;
    uint4 h, l; split8(s[0], s[1], h, l);
    ((uint4*)hi)[idx] = h; ((uint4*)lo)[idx] = l;
}

// ------------------------- HMMA GEMM -------------------------
// C[4096, N] = (Ah+Al)[4096,K] @ (Bh+Bl)[N,K]^T + b1 (+b2). 3-term bf16 split.
// 128x128 CTA tile, 8 warps (2m x 4n), K-chunks 64, cp.async double buffer,
// SW128-swizzled smem, ldmatrix + mma.sync.m16n8k16. N%128==0, K%64==0, K>=128.
__device__ __forceinline__ void gemm_load_chunk(
    const __nv_bfloat16* Ah, const __nv_bfloat16* Al,
    const __nv_bfloat16* Bh, const __nv_bfloat16* Bl,
    int m0, int n0, int K, int c, uint32_t sbase, int tid) {
    uint32_t sb = sbase + (c & 1) * 65536;
    int kb = c << 6;
#pragma unroll
    for (int it = 0; it < 4; it++) {
        int idx = it * 256 + tid;
        int row = idx >> 3, cc = idx & 7;
        uint32_t dst = SW128((uint32_t)(row * 128 + cc * 16));
        size_t ga = (size_t)(m0 + row) * K + kb + cc * 8;
        size_t gb = (size_t)(n0 + row) * K + kb + cc * 8;
        cp16(sb + dst,         Ah + ga);
        cp16(sb + 16384 + dst, Al + ga);
        cp16(sb + 32768 + dst, Bh + gb);
        cp16(sb + 49152 + dst, Bl + gb);
    }
    CP_COMMIT();
}

__global__ __launch_bounds__(256)
void hmma_gemm(const __nv_bfloat16* __restrict__ Ah, const __nv_bfloat16* __restrict__ Al,
               const __nv_bfloat16* __restrict__ Bh, const __nv_bfloat16* __restrict__ Bl,
               const float* __restrict__ b1, const float* __restrict__ b2,
               float* __restrict__ C, int N, int K) {
    extern __shared__ char dsm[];
    uint32_t raw = smem_u32(dsm);
    uint32_t sbase = (raw + 1023) & ~1023u;

    int tid = threadIdx.x, wid = tid >> 5, lane = tid & 31;
    int m0 = blockIdx.x << 7, n0 = blockIdx.y << 7;
    int NC = K >> 6;

    gemm_load_chunk(Ah, Al, Bh, Bl, m0, n0, K, 0, sbase, tid);
    gemm_load_chunk(Ah, Al, Bh, Bl, m0, n0, K, 1, sbase, tid);

    int wm = wid >> 2, wn = wid & 3;
    int mb = wm * 64, nb = wn * 32;

    float acc[4][4][4];
#pragma unroll
    for (int i = 0; i < 4; i++)
#pragma unroll
        for (int j = 0; j < 4; j++)
#pragma unroll
            for (int q = 0; q < 4; q++) acc[i][j][q] = 0.f;

    // per-lane ldmatrix geometry
    int a_r = mb + (lane & 15);          // + mt*16 ; chunk-col bit:
    int a_cb = lane >> 4;                // cc = kt*2 + a_cb
    int b_r = nb + (lane & 7) + ((lane >> 4) << 3);   // + nt2*16
    int b_cb = (lane >> 3) & 1;

    for (int c = 0; c < NC; c++) {
        if (c + 1 < NC) { CP_WAIT(1); } else { CP_WAIT(0); }
        __syncthreads();
        uint32_t sb = sbase + (c & 1) * 65536;
#pragma unroll
        for (int kt = 0; kt < 4; kt++) {
            unsigned ah[4][4], al[4][4], bh[2][4], bl[2][4];
#pragma unroll
            for (int mt = 0; mt < 4; mt++) {
                int r = a_r + mt * 16;
                uint32_t off = (uint32_t)(r * 128)
                             + ((((uint32_t)(kt * 2 + a_cb)) ^ ((uint32_t)r & 7)) << 4);
                ldsm_x4(ah[mt], sb + off);
                ldsm_x4(al[mt], sb + 16384 + off);
            }
#pragma unroll
            for (int nt2 = 0; nt2 < 2; nt2++) {
                int r = b_r + nt2 * 16;
                uint32_t off = (uint32_t)(r * 128)
                             + ((((uint32_t)(kt * 2 + b_cb)) ^ ((uint32_t)r & 7)) << 4);
                ldsm_x4(bh[nt2], sb + 32768 + off);
                ldsm_x4(bl[nt2], sb + 49152 + off);
            }
#pragma unroll
            for (int mt = 0; mt < 4; mt++)
#pragma unroll
                for (int nt = 0; nt < 4; nt++) {
                    const unsigned* bhp = &bh[nt >> 1][(nt & 1) * 2];
                    const unsigned* blp = &bl[nt >> 1][(nt & 1) * 2];
                    mma_bf16(acc[mt][nt], ah[mt], bhp);
                    mma_bf16(acc[mt][nt], ah[mt], blp);
                    mma_bf16(acc[mt][nt], al[mt], bhp);
                }
        }
        __syncthreads();
        if (c + 2 < NC)
            gemm_load_chunk(Ah, Al, Bh, Bl, m0, n0, K, c + 2, sbase, tid);
    }

    // epilogue: d-frag (row = lane/4 (+8), col = 2*(lane%3..)), direct STG.64
    int er = lane >> 2;
    int ec = (lane & 3) << 1;
#pragma unroll
    for (int nt = 0; nt < 4; nt++) {
        int col = n0 + nb + nt * 8 + ec;
        float2 bv = *(const float2*)(b1 + col);
        if (b2) {
            float2 t2 = *(const float2*)(b2 + col);
            bv.x += t2.x; bv.y += t2.y;
        }
#pragma unroll
        for (int mt = 0; mt < 4; mt++) {
            int r0 = m0 + mb + mt * 16 + er;
            *(float2*)(C + (size_t)r0 * N + col) =
                make_float2(acc[mt][nt][0] + bv.x, acc[mt][nt][1] + bv.y);
            *(float2*)(C + (size_t)(r0 + 8) * N + col) =
                make_float2(acc[mt][nt][2] + bv.x, acc[mt][nt][3] + bv.y);
        }
    }
}

// ------------------------- persistent LSTM layer -------------------------
// 128 blocks x 256 thr. Block owns 32 W_hh rows (4 gates x 8 cols).
// W_hh slice lives in REGISTERS (64 packed f32x2 row-pairs per thread, loaded
// once per layer). h duplicated into SMEM per step, read as broadcast LDS.128.
// Thread = (warp w, kh) -> k-slice of 64; lane rp -> row-pair. 16-way k-reduce
// via padded SMEM stage. One grid barrier per step.
__global__ __launch_bounds__(256)
void lstm_layer(const float* __restrict__ Whh, const float* __restrict__ gatesx,
                const float* __restrict__ h0l, const float* __restrict__ c0l,
                float* __restrict__ hs, float* __restrict__ hT, float* __restrict__ cT) {
    extern __shared__ char lsm[];
    ull* h_dup = (ull*)lsm;                          // [16][LROW] (bank-permuted)
    ull* stage = (ull*)(lsm + 16 * LROW * 8);        // [16][16][17] padded
    __shared__ float gate_sm[32][17];
    __shared__ float c_sm[128];
    __shared__ unsigned base_sh;

    int tid = threadIdx.x, bid = blockIdx.x;
    int w = tid >> 5, lane = tid & 31;
    int rp = lane & 15, kh = lane >> 4;
    int k0 = w * 128 + kh * 64;
    int s_idx = w * 2 + kh;

    if (tid == 0) base_sh = g_gen;
    __syncthreads();
    unsigned tgt = base_sh;

    // W_hh preload into registers: rows {2rp, 2rp+1} of block slice, k in [k0,k0+64)
    int l0 = 2 * rp;
    int grow0 = (l0 >> 3) * HIDDEN + bid * 8 + (l0 & 7);
    const float* w0p = Whh + (size_t)grow0 * HIDDEN + k0;
    const float* w1p = Whh + (size_t)(grow0 + 1) * HIDDEN + k0;
    ull wp[64];
#pragma unroll
    for (int j = 0; j < 16; j++) {
        float4 wa = *(const float4*)(w0p + 4 * j);
        float4 wb = *(const float4*)(w1p + 4 * j);
        wp[4*j+0] = pack_pair(wa.x, wb.x);
        wp[4*j+1] = pack_pair(wa.y, wb.y);
        wp[4*j+2] = pack_pair(wa.z, wb.z);
        wp[4*j+3] = pack_pair(wa.w, wb.w);
    }

    if (tid < 128) {
        g_hbuf[0][bid * 128 + tid] = h0l[bid * 128 + tid];
        c_sm[tid] = c0l[(tid >> 3) * HIDDEN + bid * 8 + (tid & 7)];
    }
    grid_bar(++tgt);

    int p0 = k0 + ((k0 >> 4) << 1);       // permuted base offset
    int pf = tid * 4 + ((tid >> 2) << 1); // permuted fill offset

    for (int t = 0; t < SEQ; t++) {
        const float* hin  = g_hbuf[t & 1];
        float*       hout = g_hbuf[(t + 1) & 1];

        // fill h_dup[b][perm(k)] with duplicated f32x2 pairs
#pragma unroll
        for (int u = 0; u < 16; u++) {
            float4 v = __ldcg((const float4*)(hin + u * HIDDEN + tid * 4));
            ull* d = h_dup + u * LROW + pf;
            *(ulonglong2*)d       = make_ulonglong2(pack_dup(v.x), pack_dup(v.y));
            *(ulonglong2*)(d + 2) = make_ulonglong2(pack_dup(v.z), pack_dup(v.w));
        }
        __syncthreads();

        // hot loop: 16 batches x 64 k, W in regs, h broadcast from SMEM
#pragma unroll 2
        for (int b = 0; b < 16; b++) {
            const ull* hp = h_dup + b * LROW + p0;
            ull a = 0ull;
#pragma unroll
            for (int kk = 0; kk < 64; kk += 2) {
                ulonglong2 h2 = *(const ulonglong2*)(hp + kk + ((kk >> 4) << 1));
                ffma2(a, wp[kk],     h2.x);
                ffma2(a, wp[kk + 1], h2.y);
            }
            stage[(s_idx * 16 + rp) * 17 + b] = a;
        }
        __syncthreads();

        // reduce 16 k-slices
        {
            int rp_o = tid >> 4, b_o = tid & 15;
            float sx = 0.f, sy = 0.f;
#pragma unroll
            for (int q2 = 0; q2 < 16; q2++) {
                float2 v = unpack2(stage[(q2 * 16 + rp_o) * 17 + b_o]);
                sx += v.x; sy += v.y;
            }
            gate_sm[2 * rp_o][b_o]     = sx;
            gate_sm[2 * rp_o + 1][b_o] = sy;
        }
        __syncthreads();

        if (tid < 128) {
            int b = tid >> 3, cc = tid & 7;
            int colp = bid * 8 + cc;
            size_t gb = (size_t)(b * SEQ + t) * GATES;
            float gi = gate_sm[cc][b]      + gatesx[gb + colp];
            float gf = gate_sm[8 + cc][b]  + gatesx[gb + 1024 + colp];
            float gg = gate_sm[16 + cc][b] + gatesx[gb + 2048 + colp];
            float go = gate_sm[24 + cc][b] + gatesx[gb + 3072 + colp];
            float si = 1.f / (1.f + expf(-gi));
            float sf = 1.f / (1.f + expf(-gf));
            float tg = tanhf(gg);
            float so = 1.f / (1.f + expf(-go));
            float cn = sf * c_sm[tid] + si * tg;
            c_sm[tid] = cn;
            float hn = so * tanhf(cn);
            hout[b * HIDDEN + colp] = hn;
            hs[(size_t)(b * SEQ + t) * HIDDEN + colp] = hn;
        }
        grid_bar(++tgt);
    }
    if (tid < 128) {
        hT[bid * 128 + tid] = __ldcg(&g_hbuf[0][bid * 128 + tid]);
        cT[(tid >> 3) * HIDDEN + bid * 8 + (tid & 7)] = c_sm[tid];
    }
}

// ------------------------- launch -------------------------
extern "C" void kernel_launch(void* const* d_in, const int* in_sizes, int n_in,
                              void* d_out, int out_size) {
    const int*   x     = (const int*)  d_in[0];
    const float* h0    = (const float*)d_in[1];
    const float* c0    = (const float*)d_in[2];
    const float* emb   = (const float*)d_in[3];
    const float* W_ih0 = (const float*)d_in[4];
    const float* W_hh0 = (const float*)d_in[5];
    const float* b_ih0 = (const float*)d_in[6];
    const float* b_hh0 = (const float*)d_in[7];
    const float* W_ih1 = (const float*)d_in[8];
    const float* W_hh1 = (const float*)d_in[9];
    const float* b_ih1 = (const float*)d_in[10];
    const float* b_hh1 = (const float*)d_in[11];
    const float* fc_W  = (const float*)d_in[12];
    const float* fc_b  = (const float*)d_in[13];

    float* out    = (float*)d_out;
    float* logits = out;
    float* hT     = out + (size_t)MROWS * VOCAB;
    float* cT     = hT + 2 * BATCH * HIDDEN;

    float *p_gatesx, *p_hs0, *p_hs1;
    __nv_bfloat16 *p_ah, *p_al, *p_wh, *p_wl;
    cudaGetSymbolAddress((void**)&p_gatesx, g_gatesx);
    cudaGetSymbolAddress((void**)&p_hs0, g_hs0);
    cudaGetSymbolAddress((void**)&p_hs1, g_hs1);
    cudaGetSymbolAddress((void**)&p_ah, g_ah);
    cudaGetSymbolAddress((void**)&p_al, g_al);
    cudaGetSymbolAddress((void**)&p_wh, g_wh);
    cudaGetSymbolAddress((void**)&p_wl, g_wl);

    const int GSM = 1024 + 2 * 65536;                      // hmma_gemm dyn smem
    const int LSM = 16 * LROW * 8 + 16 * 16 * 17 * 8;      // lstm dyn smem
    cudaFuncSetAttribute(hmma_gemm, cudaFuncAttributeMaxDynamicSharedMemorySize, GSM);
    cudaFuncSetAttribute(lstm_layer, cudaFuncAttributeMaxDynamicSharedMemorySize, LSM);

    const int SH = BATCH * HIDDEN;

    // layer 0
    embed_cvt<<<MROWS * 64 / 256, 256>>>(x, emb, p_ah, p_al);
    cvt_hilo<<<GATES * EMBED / 8 / 256, 256>>>(W_ih0, p_wh, p_wl, GATES * EMBED / 8);
    hmma_gemm<<<dim3(MROWS / 128, GATES / 128), 256, GSM>>>(
        p_ah, p_al, p_wh, p_wl, b_ih0, b_hh0, p_gatesx, GATES, EMBED);
    lstm_layer<<<NBLK, 256, LSM>>>(W_hh0, p_gatesx, h0, c0, p_hs0, hT, cT);

    // layer 1
    cvt_hilo<<<MROWS * HIDDEN / 8 / 256, 256>>>(p_hs0, p_ah, p_al, MROWS * HIDDEN / 8);
    cvt_hilo<<<GATES * HIDDEN / 8 / 256, 256>>>(W_ih1, p_wh, p_wl, GATES * HIDDEN / 8);
    hmma_gemm<<<dim3(MROWS / 128, GATES / 128), 256, GSM>>>(
        p_ah, p_al, p_wh, p_wl, b_ih1, b_hh1, p_gatesx, GATES, HIDDEN);
    lstm_layer<<<NBLK, 256, LSM>>>(W_hh1, p_gatesx, h0 + SH, c0 + SH, p_hs1, hT + SH, cT + SH);

    // FC head
    cvt_hilo<<<MROWS * HIDDEN / 8 / 256, 256>>>(p_hs1, p_ah, p_al, MROWS * HIDDEN / 8);
    cvt_hilo<<<VOCAB * HIDDEN / 8 / 256, 256>>>(fc_W, p_wh, p_wl, VOCAB * HIDDEN / 8);
    hmma_gemm<<<dim3(MROWS / 128, VOCAB / 128), 256, GSM>>>(
        p_ah, p_al, p_wh, p_wl, fc_b, nullptr, logits, VOCAB, HIDDEN);
}